// round 13
// baseline (speedup 1.0000x reference)
#include <cuda_runtime.h>
#include <cuda_bf16.h>
#include <math.h>
#include <stdint.h>

#define NH    32
#define LLEN  4096
#define BW    72      // words per b-row in smem B (64 tf32 words + 8 pad)

struct C2 { float r, i; };

static __device__ __forceinline__ C2 cmul(C2 a, C2 b) {
    return { a.r * b.r - a.i * b.i, a.r * b.i + a.i * b.r };
}

// fp32 phase reduction: exact Dekker product + 3-term Cody-Waite (R6-proven)
static __device__ __forceinline__ float reduce2pi(float yi, float lf) {
    const float INV2PI = 0.15915494309189534f;
    const float PI2_A  = 6.28125f;
    const float PI2_B  = 1.93500518798828125e-3f;
    const float PI2_C  = 3.0199159819568e-7f;
    const float p  = yi * lf;
    const float pe = fmaf(yi, lf, -p);
    const float k  = rintf(p * INV2PI);
    const float t0 = fmaf(-k, PI2_A, p);
    const float t1 = fmaf(-k, PI2_B, t0);
    return fmaf(-k, PI2_C, t1) + pe;
}

static __device__ __forceinline__ C2 zpow(float xr, float yi, float lf) {
    const float red = reduce2pi(yi, lf);
    float sf, cf;
    __sincosf(red, &sf, &cf);
    const float ef = __expf(xr * lf);
    return { ef * cf, ef * sf };
}

static __device__ __forceinline__ uint32_t tf32(float f) {
    uint32_t u;
    asm("cvt.rna.tf32.f32 %0, %1;" : "=r"(u) : "f"(f));
    return u;
}

static __device__ __forceinline__ void mma_tf32(
    float& d0, float& d1, float& d2, float& d3,
    uint32_t a0, uint32_t a1, uint32_t a2, uint32_t a3,
    uint32_t b0, uint32_t b1)
{
    asm volatile(
        "mma.sync.aligned.m16n8k8.row.col.f32.tf32.tf32.f32 "
        "{%0,%1,%2,%3}, {%4,%5,%6,%7}, {%8,%9}, {%0,%1,%2,%3};"
        : "+f"(d0), "+f"(d1), "+f"(d2), "+f"(d3)
        : "r"(a0), "r"(a1), "r"(a2), "r"(a3), "r"(b0), "r"(b1));
}

// word position of k-offset e within an 8-word chunk: thread t LDS.64 at 2t gets (e=t, e=t+4)
static __device__ __forceinline__ int posmap(int e) { return (e & 3) * 2 + (e >> 2); }

__global__ __launch_bounds__(128, 8) void s4d_mma_kernel(
    const float* __restrict__ log_dt,
    const float* __restrict__ C_real,
    const float* __restrict__ log_A_real,
    const float* __restrict__ A_imag,
    float* __restrict__ out)
{
    __shared__ float sxr[NH], syi[NH], scdr[NH], scdi[NH];
    // anchor tables: [0]=z^i, [1]=Cd*z^(8j), [2]=z^(64i), [3]=z^(512j)
    __shared__ __align__(16) float2 sTab[4][NH][8];     // 8 KB
    // B: 64 rows x 72 words tf32, K layout k=32c+n, chunk kc words permuted by posmap.
    // Overlaid later by Dt[64][68] f32 (17408 B <= 18432 B).
    __shared__ __align__(16) uint32_t sBw[64 * BW];     // 18432 B

    const int h   = blockIdx.x;
    const int tid = threadIdx.x;

    // ---- phase 1: per-n scalars (warp 0) -------------------------------------
    if (tid < NH) {
        const int n = tid;
        const float dt  = expf(log_dt[h]);
        const float Arf = -expf(log_A_real[h * NH + n]);
        const float Aif = A_imag[h * NH + n];
        const float xr  = dt * Arf;          // matches reference f32 product
        const float yi  = dt * Aif;

        const float em1 = expm1f(xr);
        float sy, cy;
        sincosf(yi, &sy, &cy);
        const float sh   = sinf(0.5f * yi);
        const float numr = em1 * cy - 2.0f * sh * sh;   // e^x cos y - 1
        const float numi = (1.0f + em1) * sy;           // e^x sin y
        const float invd = 1.0f / (Arf * Arf + Aif * Aif);
        const float tr = (numr * Arf + numi * Aif) * invd;
        const float ti = (numi * Arf - numr * Aif) * invd;
        const float Cr = C_real[(h * NH + n) * 2 + 0];
        const float Ci = C_real[(h * NH + n) * 2 + 1];
        scdr[n] = 2.0f * (Cr * tr - Ci * ti);
        scdi[n] = 2.0f * (Cr * ti + Ci * tr);
        sxr[n] = xr;
        syi[n] = yi;
    }
    __syncthreads();

    // ---- phase 2: anchor tables, 8 independent zpow per thread ---------------
    {
        #pragma unroll
        for (int q = 0; q < 8; q++) {
            const int f   = q * 128 + tid;     // 0..1023
            const int tab = f >> 8;            // 0..3
            const int sub = f & 255;
            const int n   = sub >> 3;
            const int i   = sub & 7;
            const int mul = (tab == 0) ? 1 : (tab == 1) ? 8 : (tab == 2) ? 64 : 512;
            C2 zv = zpow(sxr[n], syi[n], (float)(mul * i));
            if (tab == 1) zv = cmul(C2{ scdr[n], scdi[n] }, zv);
            sTab[tab][n][i] = make_float2(zv.r, zv.i);
        }
    }
    __syncthreads();

    // ---- B producer: rows (bl, bl+32), n-block g = tid>>5, rotated e ---------
    {
        const int bl = tid & 31;
        const int g  = tid >> 5;
        const int bi = bl & 7;
        const int bj = bl >> 3;
        #pragma unroll
        for (int j = 0; j < 8; j++) {
            const int e = (j + bl + (bl >> 3)) & 7;   // rotation: conflict-free STS
            const int n = 8 * g + e;
            const float2 tc  = sTab[2][n][bi];
            const float2 td  = sTab[3][n][bj];
            const float2 td2 = sTab[3][n][bj + 4];
            const C2 q  = cmul(C2{ td.x,  td.y  }, C2{ tc.x, tc.y });  // z^(64*bl)
            const C2 qh = cmul(C2{ td2.x, td2.y }, C2{ tc.x, tc.y });  // z^(64*(bl+32))
            const int pr = g * 8 + posmap(e);          // real chunk kc=g
            const int pi = (g + 4) * 8 + posmap(e);    // imag chunk kc=g+4
            sBw[bl * BW + pr]        = tf32(q.r);
            sBw[bl * BW + pi]        = tf32(q.i);
            sBw[(bl + 32) * BW + pr] = tf32(qh.r);
            sBw[(bl + 32) * BW + pi] = tf32(qh.i);
        }
    }
    __syncthreads();

    // ---- MMA mainloop: kc' outer, tf32 single pass ---------------------------
    const int w = tid >> 5;        // warp -> rows 16w..16w+15
    const int r = (tid >> 2) & 7;  // lane/4
    const int t = tid & 3;         // lane%4

    float d[8][4];
    #pragma unroll
    for (int nt = 0; nt < 8; nt++)
        #pragma unroll
        for (int c = 0; c < 4; c++) d[nt][c] = 0.0f;

    #pragma unroll
    for (int kc = 0; kc < 4; kc++) {
        // A fragments: n1 = 8kc+t, n2 = n1+4; rows a=16w+r and a+8
        const int n1 = 8 * kc + t;
        const int n2 = n1 + 4;
        const float2 ta1  = sTab[0][n1][r];
        const float2 tb10 = sTab[1][n1][2 * w];
        const float2 tb11 = sTab[1][n1][2 * w + 1];
        const float2 ta2  = sTab[0][n2][r];
        const float2 tb20 = sTab[1][n2][2 * w];
        const float2 tb21 = sTab[1][n2][2 * w + 1];
        const C2 p1a = cmul(C2{ tb10.x, tb10.y }, C2{ ta1.x, ta1.y });  // Cd*z^a     (n1)
        const C2 p1b = cmul(C2{ tb11.x, tb11.y }, C2{ ta1.x, ta1.y });  // Cd*z^(a+8) (n1)
        const C2 p2a = cmul(C2{ tb20.x, tb20.y }, C2{ ta2.x, ta2.y });
        const C2 p2b = cmul(C2{ tb21.x, tb21.y }, C2{ ta2.x, ta2.y });

        const uint32_t Ar0 = tf32(p1a.r), Ar1 = tf32(p1b.r), Ar2 = tf32(p2a.r), Ar3 = tf32(p2b.r);
        const uint32_t Ai0 = tf32(-p1a.i), Ai1 = tf32(-p1b.i), Ai2 = tf32(-p2a.i), Ai3 = tf32(-p2b.i);

        #pragma unroll
        for (int nt = 0; nt < 8; nt++) {
            const int base = (8 * nt + r) * BW;
            const uint2 br = *(const uint2*)&sBw[base + kc * 8 + t * 2];        // Qr: k=t, t+4
            const uint2 bi = *(const uint2*)&sBw[base + (kc + 4) * 8 + t * 2];  // Qi
            mma_tf32(d[nt][0], d[nt][1], d[nt][2], d[nt][3],
                     Ar0, Ar1, Ar2, Ar3, br.x, br.y);
            mma_tf32(d[nt][0], d[nt][1], d[nt][2], d[nt][3],
                     Ai0, Ai1, Ai2, Ai3, bi.x, bi.y);
        }
    }
    __syncthreads();   // all B reads done before Dt overlay

    // ---- stage D[a][b] -> Dt[b][a] (pad 68 words: conflict-free writes) ------
    float (*Dt)[68] = reinterpret_cast<float(*)[68]>(sBw);
    {
        const int ar = 16 * w + r;
        #pragma unroll
        for (int nt = 0; nt < 8; nt++) {
            const int bc = 8 * nt + 2 * t;
            Dt[bc    ][ar    ] = d[nt][0];
            Dt[bc + 1][ar    ] = d[nt][1];
            Dt[bc    ][ar + 8] = d[nt][2];
            Dt[bc + 1][ar + 8] = d[nt][3];
        }
    }
    __syncthreads();

    // ---- coalesced vector store: out[h][b*64+a] ------------------------------
    float* outh = out + (size_t)h * LLEN;
    #pragma unroll
    for (int it = 0; it < 8; it++) {
        const int idx = it * 512 + tid * 4;
        const float4 v = *(const float4*)&Dt[idx >> 6][idx & 63];
        *(float4*)&outh[idx] = v;
    }
}

extern "C" void kernel_launch(void* const* d_in, const int* in_sizes, int n_in,
                              void* d_out, int out_size)
{
    const float* log_dt     = (const float*)d_in[0];
    const float* C_real     = (const float*)d_in[1];
    const float* log_A_real = (const float*)d_in[2];
    const float* A_imag     = (const float*)d_in[3];
    float* out = (float*)d_out;
    s4d_mma_kernel<<<1024, 128>>>(log_dt, C_real, log_A_real, A_imag, out);
}